// round 8
// baseline (speedup 1.0000x reference)
#include <cuda_runtime.h>
#include <cuda_fp16.h>
#include <cstdint>

#define B_SZ 8192
#define I_SZ 256
#define O_SZ 256
#define C_SZ 32
#define FULLMASK 0xFFFFFFFFu
#define MAX_TILES 96
#define NB 148

// ---------------- scratch (device globals; allocation-free) ----------------
__device__ int g_perm[B_SZ];
__device__ int g_offset[C_SZ];
__device__ int g_tiles[MAX_TILES];
__device__ int g_ntiles;
__device__ int g_is64;
__device__ int g_ok64[32];
__device__ int g_h64[32 * 8 * 32];
__device__ int g_h32[32 * 8 * 32];
__device__ int g_wcur[256 * 32];
__device__ __half g_wq[C_SZ * O_SZ * I_SZ];
__device__ __half g_xp[(B_SZ + 128) * I_SZ];

// ---------------- software grid barrier (sense-reversing, monotonic) -------
__device__ unsigned g_bcnt[4];
__device__ volatile unsigned g_bgen[4];

__device__ __forceinline__ void grid_bar(int i) {
    __syncthreads();
    if (threadIdx.x == 0) {
        unsigned my = g_bgen[i];
        __threadfence();
        if (atomicAdd(&g_bcnt[i], 1u) == NB - 1) {
            g_bcnt[i] = 0;
            __threadfence();
            g_bgen[i] = my + 1;
        } else {
            while (g_bgen[i] == my) {}
            __threadfence();
        }
    }
    __syncthreads();
}

// ---------------- gemm plumbing ----------------
#define RB 144
#define A_CH (128 * RB)
#define STAGE (2 * A_CH)
#define OFF_ROW  0
#define OFF_BIAS 512
#define OFF_PIPE 1024
#define SM_TOTAL (OFF_PIPE + 3 * STAGE)   // 111616

__device__ __forceinline__ uint32_t smem_u32(const void* p) {
    uint32_t a;
    asm("{ .reg .u64 t; cvta.to.shared.u64 t, %1; cvt.u32.u64 %0, t; }"
        : "=r"(a) : "l"(p));
    return a;
}

#define CP16(dst, src) \
    asm volatile("cp.async.cg.shared.global [%0], [%1], 16;" \
                 :: "r"(dst), "l"(src) : "memory")
#define CP_COMMIT() asm volatile("cp.async.commit_group;" ::: "memory")
#define CP_WAIT(n)  asm volatile("cp.async.wait_group %0;" :: "n"(n) : "memory")

#define LDSM_X4(r0, r1, r2, r3, addr)                                       \
    asm volatile("ldmatrix.sync.aligned.m8n8.x4.shared.b16 "                \
                 "{%0,%1,%2,%3}, [%4];"                                     \
                 : "=r"(r0), "=r"(r1), "=r"(r2), "=r"(r3) : "r"(addr))

#define MMA16816(d0, d1, d2, d3, a0, a1, a2, a3, b0, b1)                    \
    asm volatile("mma.sync.aligned.m16n8k16.row.col.f32.f16.f16.f32 "       \
                 "{%0,%1,%2,%3}, {%4,%5,%6,%7}, {%8,%9}, {%0,%1,%2,%3};"    \
                 : "+f"(d0), "+f"(d1), "+f"(d2), "+f"(d3)                   \
                 : "r"(a0), "r"(a1), "r"(a2), "r"(a3), "r"(b0), "r"(b1))

// ---------------------------------------------------------------------------
// THE kernel: count‖conv_w -> prefix -> scatter -> gather -> persistent GEMM
// ---------------------------------------------------------------------------
__global__ __launch_bounds__(256, 1)
void mega_kernel(const float* __restrict__ x,
                 const void* __restrict__ idx_ptr,
                 const float* __restrict__ weight,
                 const float* __restrict__ bias,
                 float* __restrict__ out) {
    extern __shared__ char smem[];
    const int b = blockIdx.x;
    const int tid = threadIdx.x;
    const int w = tid >> 5;
    const int lane = tid & 31;
    const uint32_t sb = smem_u32(smem);

    // ================= Phase 1: count (b<32)  ||  conv_w (b>=32) ==========
    if (b < 32) {
        int* s_h64 = (int*)smem;            // [8][32]
        int* s_h32 = s_h64 + 256;
        int* s_vote = s_h32 + 256;
        if (w == 0 && lane < 8) s_vote[lane] = 0;
        s_h64[w * 32 + lane] = 0;
        s_h32[w * 32 + lane] = 0;
        __syncthreads();

        const int e = b * 256 + tid;
        const int v32 = ((const int*)idx_ptr)[e];
        const int2 v64 = ((const int2*)idx_ptr)[e];

        int ok64 = (v64.y == 0) && ((unsigned)v64.x < 32u);
        int allok = __all_sync(FULLMASK, ok64);
        if (lane == 0) s_vote[w] = allok;
        {
            int c = v64.x & 31;
            unsigned m = __match_any_sync(FULLMASK, c);
            if (lane == (__ffs(m) - 1)) s_h64[w * 32 + c] += __popc(m);
        }
        {
            int c = v32 & 31;
            unsigned m = __match_any_sync(FULLMASK, c);
            if (lane == (__ffs(m) - 1)) s_h32[w * 32 + c] += __popc(m);
        }
        __syncthreads();
        if (tid == 0) {
            int a = 1;
#pragma unroll
            for (int i = 0; i < 8; i++) a &= s_vote[i];
            g_ok64[b] = a;
        }
        g_h64[b * 256 + tid] = s_h64[w * 32 + lane];
        g_h32[b * 256 + tid] = s_h32[w * 32 + lane];
    } else {
        __half* sh = (__half*)smem;         // [256*33] = 16896 B
        for (int o = b - 32; o < 256; o += 116) {
            const float* src = weight + (size_t)o * (I_SZ * C_SZ);
            __syncthreads();
            for (int l = tid; l < I_SZ * C_SZ; l += 256) {
                int i = l >> 5, c = l & 31;
                sh[i * 33 + c] = __float2half_rn(src[l]);
            }
            __syncthreads();
            for (int u = tid; u < (I_SZ * C_SZ) / 4; u += 256) {
                int c = u >> 6, i4 = u & 63;
                union { uint2 uu; __half h[4]; } H;
#pragma unroll
                for (int j = 0; j < 4; j++)
                    H.h[j] = sh[(i4 * 4 + j) * 33 + c];
                size_t off = ((size_t)c << 16) + ((size_t)o << 8) + (size_t)i4 * 4;
                *(uint2*)(g_wq + off) = H.uu;
            }
        }
    }
    grid_bar(0);

    // ================= Phase 2: prefix + cursors + tiles (block 0) ========
    if (b == 0) {
        int* s_cur = (int*)smem;            // 8192 ints = 32 KB
        int* s_tot = s_cur + 8192;
        int* s_off = s_tot + 32;
        int* s_flg = s_off + 32;

        if (tid < 32) {
            int v = g_ok64[tid];
            v = __all_sync(FULLMASK, v);
            if (tid == 0) { s_flg[0] = v; g_is64 = v; }
        }
        __syncthreads();
        const int* H = s_flg[0] ? g_h64 : g_h32;

#pragma unroll
        for (int cc = 0; cc < 4; cc++) {
            const int c = w * 4 + cc;
            int carry = 0;
#pragma unroll
            for (int r = 0; r < 8; r++) {
                int wq = r * 32 + lane;
                int v = H[wq * 32 + c];
                int incl = v;
#pragma unroll
                for (int d = 1; d < 32; d <<= 1) {
                    int u = __shfl_up_sync(FULLMASK, incl, d);
                    if (lane >= d) incl += u;
                }
                s_cur[wq * 32 + c] = carry + (incl - v);
                carry += __shfl_sync(FULLMASK, incl, 31);
            }
            if (lane == 0) s_tot[c] = carry;
        }
        __syncthreads();

        if (tid < 32) {
            int v = s_tot[tid];
            int incl = v;
#pragma unroll
            for (int d = 1; d < 32; d <<= 1) {
                int u = __shfl_up_sync(FULLMASK, incl, d);
                if (lane >= d) incl += u;
            }
            int off = incl - v;
            s_off[tid] = off;
            g_offset[tid] = off;
        }
        __syncthreads();

        if (tid == 0) {
            int nt = 0;
            for (int c = 0; c < 32; c++) {
                int cnt = s_tot[c];
                for (int m = 0; m * 128 < cnt; m++) {
                    int rows = min(128, cnt - m * 128);
                    g_tiles[nt++] = c | (m << 8) | (rows << 16);
                }
            }
            g_ntiles = nt;
        }
        __syncthreads();
#pragma unroll
        for (int i = 0; i < 32; i++) {
            int idx = tid + i * 256;
            g_wcur[idx] = s_cur[idx] + s_off[idx & 31];
        }
    }
    grid_bar(1);

    // ================= Phase 3: scatter (blocks 0..31) ====================
    if (b < 32) {
        const int e = b * 256 + tid;
        const int is64 = g_is64;
        int c = is64 ? (((const int2*)idx_ptr)[e].x & 31)
                     : (((const int*)idx_ptr)[e] & 31);
        unsigned m = __match_any_sync(FULLMASK, c);
        int rank = __popc(m & ((1u << lane) - 1u));
        int base = g_wcur[(b * 8 + w) * 32 + c];
        g_perm[base + rank] = e;
    }
    grid_bar(2);

    // ================= Phase 4: gather x -> g_xp (all blocks) =============
    for (int t = b * 256 + tid; t < B_SZ * 32; t += NB * 256) {
        int row = t >> 5, g = t & 31;
        int src_row = g_perm[row];
        const float4* src = (const float4*)(x + (size_t)src_row * I_SZ + g * 8);
        float4 v0 = src[0], v1 = src[1];
        union { uint4 u; __half2 h[4]; } P;
        P.h[0] = __float22half2_rn(make_float2(v0.x, v0.y));
        P.h[1] = __float22half2_rn(make_float2(v0.z, v0.w));
        P.h[2] = __float22half2_rn(make_float2(v1.x, v1.y));
        P.h[3] = __float22half2_rn(make_float2(v1.z, v1.w));
        *(uint4*)(g_xp + (size_t)row * I_SZ + g * 8) = P.u;
    }
    grid_bar(3);

    // ================= Phase 5: persistent GEMM ===========================
    const int njobs = g_ntiles * 2;
    const int wm = w >> 2;
    const int wn = w & 3;
    int* s_row = (int*)(smem + OFF_ROW);
    float* s_bias = (float*)(smem + OFF_BIAS);

    uint32_t aoff[4], boff[2];
#pragma unroll
    for (int mt = 0; mt < 4; mt++)
        aoff[mt] = (wm * 64 + mt * 16 + (lane & 15)) * RB + (lane >> 4) * 16;
#pragma unroll
    for (int p = 0; p < 2; p++)
        boff[p] = (wn * 32 + p * 16 + (lane >> 4) * 8 + (lane & 7)) * RB +
                  ((lane >> 3) & 1) * 16;

    for (int j = b; j < njobs; j += NB) {
        __syncthreads();   // smem safe across jobs
        const int t = g_tiles[j >> 1];
        const int c = t & 31;
        const int m0 = ((t >> 8) & 0xFF) * 128;
        const int rows = (t >> 16) & 0xFF;
        const int base = g_offset[c] + m0;
        const int n0 = (j & 1) * 128;

        if (tid < 128) {
            s_row[tid] = g_perm[base + min(tid, rows - 1)];
            s_bias[tid] = bias[(size_t)(n0 + tid) * C_SZ + c];
        }

        const __half* asrc0 = g_xp + (size_t)base * I_SZ;
        const __half* wsrc0 = g_wq + ((size_t)c << 16) + (size_t)n0 * I_SZ;

        auto fill = [&](int kc, int stage) {
            const uint32_t dstA = sb + OFF_PIPE + stage * STAGE;
            const uint32_t dstW = dstA + A_CH;
            const __half* sa = asrc0 + kc * 64;
            const __half* sw = wsrc0 + kc * 64;
#pragma unroll
            for (int it = 0; it < 4; it++) {
                int task = tid + it * 256;
                int r = task >> 3, g = task & 7;
                CP16(dstA + r * RB + g * 16, sa + (size_t)r * I_SZ + g * 8);
            }
#pragma unroll
            for (int it = 0; it < 4; it++) {
                int task = tid + it * 256;
                int r = task >> 3, g = task & 7;
                CP16(dstW + r * RB + g * 16, sw + (size_t)r * I_SZ + g * 8);
            }
            CP_COMMIT();
        };

        fill(0, 0);
        fill(1, 1);
        fill(2, 2);

        float acc[4][4][4];
#pragma unroll
        for (int i = 0; i < 4; i++)
#pragma unroll
            for (int jj = 0; jj < 4; jj++)
#pragma unroll
                for (int q = 0; q < 4; q++) acc[i][jj][q] = 0.0f;

        auto compute = [&](int stage) {
            const uint32_t ab = sb + OFF_PIPE + stage * STAGE;
            const uint32_t wb = ab + A_CH;
#pragma unroll
            for (int kk = 0; kk < 4; kk++) {
                const uint32_t kb = kk * 32;
                uint32_t a[4][4], bb[2][4];
#pragma unroll
                for (int mt = 0; mt < 4; mt++)
                    LDSM_X4(a[mt][0], a[mt][1], a[mt][2], a[mt][3],
                            ab + aoff[mt] + kb);
#pragma unroll
                for (int p = 0; p < 2; p++)
                    LDSM_X4(bb[p][0], bb[p][1], bb[p][2], bb[p][3],
                            wb + boff[p] + kb);
#pragma unroll
                for (int mt = 0; mt < 4; mt++) {
#pragma unroll
                    for (int nt = 0; nt < 4; nt++) {
                        uint32_t b0 = bb[nt >> 1][(nt & 1) * 2 + 0];
                        uint32_t b1 = bb[nt >> 1][(nt & 1) * 2 + 1];
                        MMA16816(acc[mt][nt][0], acc[mt][nt][1],
                                 acc[mt][nt][2], acc[mt][nt][3],
                                 a[mt][0], a[mt][1], a[mt][2], a[mt][3],
                                 b0, b1);
                    }
                }
            }
        };

        CP_WAIT(2);
        __syncthreads();
        compute(0);
        __syncthreads();
        fill(3, 0);
        CP_WAIT(2);
        __syncthreads();
        compute(1);
        CP_WAIT(1);
        __syncthreads();
        compute(2);
        CP_WAIT(0);
        __syncthreads();
        compute(0);

        const int g = lane >> 2, tq = lane & 3;
#pragma unroll
        for (int mt = 0; mt < 4; mt++) {
            int rl = wm * 64 + mt * 16 + g;
#pragma unroll
            for (int h = 0; h < 2; h++) {
                int rr = rl + h * 8;
                if (rr < rows) {
                    float* op = out + (size_t)s_row[rr] * O_SZ + n0;
#pragma unroll
                    for (int nt = 0; nt < 4; nt++) {
                        int cl = wn * 32 + nt * 8 + 2 * tq;
                        float2 v;
                        v.x = acc[mt][nt][h * 2 + 0] + s_bias[cl + 0];
                        v.y = acc[mt][nt][h * 2 + 1] + s_bias[cl + 1];
                        *(float2*)(op + cl) = v;
                    }
                }
            }
        }
    }
}

// ---------------------------------------------------------------------------
// launch: ONE kernel
// ---------------------------------------------------------------------------
extern "C" void kernel_launch(void* const* d_in, const int* in_sizes, int n_in,
                              void* d_out, int out_size) {
    const float* x      = (const float*)d_in[0];
    const void*  idx    = d_in[1];
    const float* weight = (const float*)d_in[2];
    const float* bias   = (const float*)d_in[3];
    float* out = (float*)d_out;

    cudaFuncSetAttribute(mega_kernel,
                         cudaFuncAttributeMaxDynamicSharedMemorySize, SM_TOTAL);
    mega_kernel<<<NB, 256, SM_TOTAL>>>(x, idx, weight, bias, out);
}

// round 9
// speedup vs baseline: 1.1498x; 1.1498x over previous
#include <cuda_runtime.h>
#include <cuda_fp16.h>
#include <cstdint>

#define B_SZ 8192
#define I_SZ 256
#define O_SZ 256
#define C_SZ 32
#define FULLMASK 0xFFFFFFFFu
#define MAX_TILES 96
#define PREP_NB 32

// ---------------- scratch (device globals; allocation-free) ----------------
__device__ int g_perm[B_SZ];
__device__ int g_offset[C_SZ];
__device__ int g_tiles[MAX_TILES];
__device__ int g_ntiles;
__device__ int g_h64[32 * 8 * 32];
__device__ int g_h32[32 * 8 * 32];
__device__ int g_ok64[32];
__device__ int g_is64;
__device__ int g_wcur[256 * 32];
__device__ __half g_wq[C_SZ * O_SZ * I_SZ];      // [c][o][i] fp16
__device__ __half g_xp[(B_SZ + 128) * I_SZ];     // permuted x fp16 (+pad)

// ---------------- small grid barrier for the 32-block prep kernel ----------
__device__ unsigned p_bcnt[2];
__device__ volatile unsigned p_bgen[2];

__device__ __forceinline__ void prep_bar(int i) {
    __syncthreads();
    if (threadIdx.x == 0) {
        unsigned my = p_bgen[i];
        __threadfence();
        if (atomicAdd(&p_bcnt[i], 1u) == PREP_NB - 1) {
            p_bcnt[i] = 0;
            __threadfence();
            p_bgen[i] = my + 1;
        } else {
            while (p_bgen[i] == my) {}
            __threadfence();
        }
    }
    __syncthreads();
}

// ---------------------------------------------------------------------------
// k_prep: 32 blocks x 256. count -> (block0) prefix/cursors/tiles -> scatter
// ---------------------------------------------------------------------------
__global__ __launch_bounds__(256, 1)
void k_prep(const void* __restrict__ idx_ptr) {
    __shared__ int s_big[8192 + 80];   // prefix workspace (block 0) / hists

    const int b = blockIdx.x;
    const int tid = threadIdx.x;
    const int w = tid >> 5;
    const int lane = tid & 31;

    // ---------- phase A: count (all 32 blocks) ----------
    {
        int* s_h64 = s_big;          // [8][32]
        int* s_h32 = s_big + 256;
        int* s_vote = s_big + 512;
        if (w == 0 && lane < 8) s_vote[lane] = 0;
        s_h64[w * 32 + lane] = 0;
        s_h32[w * 32 + lane] = 0;
        __syncthreads();

        const int e = b * 256 + tid;
        const int v32 = ((const int*)idx_ptr)[e];
        const int2 v64 = ((const int2*)idx_ptr)[e];

        int ok64 = (v64.y == 0) && ((unsigned)v64.x < 32u);
        int allok = __all_sync(FULLMASK, ok64);
        if (lane == 0) s_vote[w] = allok;
        {
            int c = v64.x & 31;
            unsigned m = __match_any_sync(FULLMASK, c);
            if (lane == (__ffs(m) - 1)) s_h64[w * 32 + c] += __popc(m);
        }
        {
            int c = v32 & 31;
            unsigned m = __match_any_sync(FULLMASK, c);
            if (lane == (__ffs(m) - 1)) s_h32[w * 32 + c] += __popc(m);
        }
        __syncthreads();
        if (tid == 0) {
            int a = 1;
#pragma unroll
            for (int i = 0; i < 8; i++) a &= s_vote[i];
            g_ok64[b] = a;
        }
        g_h64[b * 256 + tid] = s_h64[w * 32 + lane];
        g_h32[b * 256 + tid] = s_h32[w * 32 + lane];
    }
    prep_bar(0);

    // ---------- phase B: prefix + cursors + tiles (block 0 only) ----------
    if (b == 0) {
        int* s_cur = s_big;            // 8192 ints
        int* s_tot = s_big + 8192;     // 32
        int* s_off = s_tot + 32;       // 32
        int* s_flg = s_off + 32;       // 1

        if (tid < 32) {
            int v = g_ok64[tid];
            v = __all_sync(FULLMASK, v);
            if (tid == 0) { s_flg[0] = v; g_is64 = v; }
        }
        __syncthreads();
        const int* H = s_flg[0] ? g_h64 : g_h32;

#pragma unroll
        for (int cc = 0; cc < 4; cc++) {
            const int c = w * 4 + cc;
            int carry = 0;
#pragma unroll
            for (int r = 0; r < 8; r++) {
                int wq = r * 32 + lane;
                int v = H[wq * 32 + c];
                int incl = v;
#pragma unroll
                for (int d = 1; d < 32; d <<= 1) {
                    int u = __shfl_up_sync(FULLMASK, incl, d);
                    if (lane >= d) incl += u;
                }
                s_cur[wq * 32 + c] = carry + (incl - v);
                carry += __shfl_sync(FULLMASK, incl, 31);
            }
            if (lane == 0) s_tot[c] = carry;
        }
        __syncthreads();

        if (tid < 32) {
            int v = s_tot[tid];
            int incl = v;
#pragma unroll
            for (int d = 1; d < 32; d <<= 1) {
                int u = __shfl_up_sync(FULLMASK, incl, d);
                if (lane >= d) incl += u;
            }
            int off = incl - v;
            s_off[tid] = off;
            g_offset[tid] = off;
        }
        __syncthreads();

        if (tid == 0) {
            int nt = 0;
            for (int c = 0; c < 32; c++) {
                int cnt = s_tot[c];
                for (int m = 0; m * 128 < cnt; m++) {
                    int rows = min(128, cnt - m * 128);
                    g_tiles[nt++] = c | (m << 8) | (rows << 16);
                }
            }
            g_ntiles = nt;
        }
        __syncthreads();
#pragma unroll
        for (int i = 0; i < 32; i++) {
            int idx = tid + i * 256;
            g_wcur[idx] = s_cur[idx] + s_off[idx & 31];
        }
    }
    prep_bar(1);

    // ---------- phase C: scatter (all 32 blocks) ----------
    {
        const int e = b * 256 + tid;
        const int is64 = g_is64;
        int c = is64 ? (((const int2*)idx_ptr)[e].x & 31)
                     : (((const int*)idx_ptr)[e] & 31);
        unsigned m = __match_any_sync(FULLMASK, c);
        int rank = __popc(m & ((1u << lane) - 1u));
        int base = g_wcur[(b * 8 + w) * 32 + c];
        g_perm[base + rank] = e;
    }
}

// ---------------------------------------------------------------------------
// kB: blocks 0..1023 gather x->fp16 permuted; blocks 1024..1279 conv_w
// ---------------------------------------------------------------------------
__global__ __launch_bounds__(256, 1)
void kB_gather_convw(const float* __restrict__ x,
                     const float* __restrict__ weight) {
    __shared__ __half sh[I_SZ * 33];

    if (blockIdx.x < 1024) {
        const int t = blockIdx.x * 256 + threadIdx.x;
        const int row = t >> 5, g = t & 31;
        const int src_row = g_perm[row];
        const float4* src = (const float4*)(x + (size_t)src_row * I_SZ + g * 8);
        float4 v0 = src[0], v1 = src[1];
        union { uint4 u; __half2 h[4]; } P;
        P.h[0] = __float22half2_rn(make_float2(v0.x, v0.y));
        P.h[1] = __float22half2_rn(make_float2(v0.z, v0.w));
        P.h[2] = __float22half2_rn(make_float2(v1.x, v1.y));
        P.h[3] = __float22half2_rn(make_float2(v1.z, v1.w));
        *(uint4*)(g_xp + (size_t)row * I_SZ + g * 8) = P.u;
        return;
    }

    const int o = blockIdx.x - 1024;
    const int tid = threadIdx.x;
    const float* src = weight + (size_t)o * (I_SZ * C_SZ);

    for (int l = tid; l < I_SZ * C_SZ; l += 256) {
        int i = l >> 5, c = l & 31;
        sh[i * 33 + c] = __float2half_rn(src[l]);
    }
    __syncthreads();

    for (int u = tid; u < (I_SZ * C_SZ) / 4; u += 256) {
        int c = u >> 6, i4 = u & 63;
        union { uint2 uu; __half h[4]; } H;
#pragma unroll
        for (int j = 0; j < 4; j++)
            H.h[j] = sh[(i4 * 4 + j) * 33 + c];
        size_t off = ((size_t)c << 16) + ((size_t)o << 8) + (size_t)i4 * 4;
        *(uint2*)(g_wq + off) = H.uu;
    }
}

// ---------------------------------------------------------------------------
// GEMM: M=128 x N=128 x K=256, cp.async 3-stage pipeline over 4 K-chunks.
// ---------------------------------------------------------------------------
#define RB 144
#define A_CH (128 * RB)
#define STAGE (2 * A_CH)
#define OFF_ROW  0
#define OFF_BIAS 512
#define OFF_PIPE 1024
#define SM_TOTAL (OFF_PIPE + 3 * STAGE)   // 111616

__device__ __forceinline__ uint32_t smem_u32(const void* p) {
    uint32_t a;
    asm("{ .reg .u64 t; cvta.to.shared.u64 t, %1; cvt.u32.u64 %0, t; }"
        : "=r"(a) : "l"(p));
    return a;
}

#define CP16(dst, src) \
    asm volatile("cp.async.cg.shared.global [%0], [%1], 16;" \
                 :: "r"(dst), "l"(src) : "memory")
#define CP_COMMIT() asm volatile("cp.async.commit_group;" ::: "memory")
#define CP_WAIT(n)  asm volatile("cp.async.wait_group %0;" :: "n"(n) : "memory")

#define LDSM_X4(r0, r1, r2, r3, addr)                                       \
    asm volatile("ldmatrix.sync.aligned.m8n8.x4.shared.b16 "                \
                 "{%0,%1,%2,%3}, [%4];"                                     \
                 : "=r"(r0), "=r"(r1), "=r"(r2), "=r"(r3) : "r"(addr))

#define MMA16816(d0, d1, d2, d3, a0, a1, a2, a3, b0, b1)                    \
    asm volatile("mma.sync.aligned.m16n8k16.row.col.f32.f16.f16.f32 "       \
                 "{%0,%1,%2,%3}, {%4,%5,%6,%7}, {%8,%9}, {%0,%1,%2,%3};"    \
                 : "+f"(d0), "+f"(d1), "+f"(d2), "+f"(d3)                   \
                 : "r"(a0), "r"(a1), "r"(a2), "r"(a3), "r"(b0), "r"(b1))

__global__ __launch_bounds__(256, 2)
void gemm_mma_kernel(const float* __restrict__ bias, float* __restrict__ out) {
    extern __shared__ char smem[];
    if ((int)blockIdx.x >= g_ntiles) return;
    const int t = g_tiles[blockIdx.x];
    const int c = t & 31;
    const int m0 = ((t >> 8) & 0xFF) * 128;
    const int rows = (t >> 16) & 0xFF;
    const int base = g_offset[c] + m0;
    const int n0 = blockIdx.y * 128;

    const int tid = threadIdx.x;
    const int wid = tid >> 5;
    const int lane = tid & 31;
    const int wm = wid >> 2;
    const int wn = wid & 3;

    int* s_row = (int*)(smem + OFF_ROW);
    float* s_bias = (float*)(smem + OFF_BIAS);
    const uint32_t sb = smem_u32(smem);

    if (tid < 128) {
        s_row[tid] = g_perm[base + min(tid, rows - 1)];
        s_bias[tid] = bias[(size_t)(n0 + tid) * C_SZ + c];
    }

    const __half* asrc0 = g_xp + (size_t)base * I_SZ;
    const __half* wsrc0 = g_wq + ((size_t)c << 16) + (size_t)n0 * I_SZ;

    auto fill = [&](int kc, int stage) {
        const uint32_t dstA = sb + OFF_PIPE + stage * STAGE;
        const uint32_t dstW = dstA + A_CH;
        const __half* sa = asrc0 + kc * 64;
        const __half* sw = wsrc0 + kc * 64;
#pragma unroll
        for (int it = 0; it < 4; it++) {
            int task = tid + it * 256;
            int r = task >> 3, g = task & 7;
            CP16(dstA + r * RB + g * 16, sa + (size_t)r * I_SZ + g * 8);
        }
#pragma unroll
        for (int it = 0; it < 4; it++) {
            int task = tid + it * 256;
            int r = task >> 3, g = task & 7;
            CP16(dstW + r * RB + g * 16, sw + (size_t)r * I_SZ + g * 8);
        }
        CP_COMMIT();
    };

    fill(0, 0);
    fill(1, 1);
    fill(2, 2);

    float acc[4][4][4];
#pragma unroll
    for (int i = 0; i < 4; i++)
#pragma unroll
        for (int j = 0; j < 4; j++)
#pragma unroll
            for (int q = 0; q < 4; q++) acc[i][j][q] = 0.0f;

    uint32_t aoff[4], boff[2];
#pragma unroll
    for (int mt = 0; mt < 4; mt++)
        aoff[mt] = (wm * 64 + mt * 16 + (lane & 15)) * RB + (lane >> 4) * 16;
#pragma unroll
    for (int p = 0; p < 2; p++)
        boff[p] = (wn * 32 + p * 16 + (lane >> 4) * 8 + (lane & 7)) * RB +
                  ((lane >> 3) & 1) * 16;

    auto compute = [&](int stage) {
        const uint32_t ab = sb + OFF_PIPE + stage * STAGE;
        const uint32_t wb = ab + A_CH;
#pragma unroll
        for (int j = 0; j < 4; j++) {
            const uint32_t kb = j * 32;
            uint32_t a[4][4], b[2][4];
#pragma unroll
            for (int mt = 0; mt < 4; mt++)
                LDSM_X4(a[mt][0], a[mt][1], a[mt][2], a[mt][3],
                        ab + aoff[mt] + kb);
#pragma unroll
            for (int p = 0; p < 2; p++)
                LDSM_X4(b[p][0], b[p][1], b[p][2], b[p][3],
                        wb + boff[p] + kb);
#pragma unroll
            for (int mt = 0; mt < 4; mt++) {
#pragma unroll
                for (int nt = 0; nt < 4; nt++) {
                    uint32_t b0 = b[nt >> 1][(nt & 1) * 2 + 0];
                    uint32_t b1 = b[nt >> 1][(nt & 1) * 2 + 1];
                    MMA16816(acc[mt][nt][0], acc[mt][nt][1],
                             acc[mt][nt][2], acc[mt][nt][3],
                             a[mt][0], a[mt][1], a[mt][2], a[mt][3], b0, b1);
                }
            }
        }
    };

    CP_WAIT(2);
    __syncthreads();
    compute(0);
    __syncthreads();
    fill(3, 0);
    CP_WAIT(2);
    __syncthreads();
    compute(1);
    CP_WAIT(1);
    __syncthreads();
    compute(2);
    CP_WAIT(0);
    __syncthreads();
    compute(0);

    const int g = lane >> 2, tq = lane & 3;
#pragma unroll
    for (int mt = 0; mt < 4; mt++) {
        int rl = wm * 64 + mt * 16 + g;
#pragma unroll
        for (int h = 0; h < 2; h++) {
            int rr = rl + h * 8;
            if (rr < rows) {
                float* op = out + (size_t)s_row[rr] * O_SZ + n0;
#pragma unroll
                for (int nt = 0; nt < 4; nt++) {
                    int cl = wn * 32 + nt * 8 + 2 * tq;
                    float2 v;
                    v.x = acc[mt][nt][h * 2 + 0] + s_bias[cl + 0];
                    v.y = acc[mt][nt][h * 2 + 1] + s_bias[cl + 1];
                    *(float2*)(op + cl) = v;
                }
            }
        }
    }
}

// ---------------------------------------------------------------------------
// launch: 3 kernels
// ---------------------------------------------------------------------------
extern "C" void kernel_launch(void* const* d_in, const int* in_sizes, int n_in,
                              void* d_out, int out_size) {
    const float* x      = (const float*)d_in[0];
    const void*  idx    = d_in[1];
    const float* weight = (const float*)d_in[2];
    const float* bias   = (const float*)d_in[3];
    float* out = (float*)d_out;

    cudaFuncSetAttribute(gemm_mma_kernel,
                         cudaFuncAttributeMaxDynamicSharedMemorySize, SM_TOTAL);

    k_prep<<<PREP_NB, 256>>>(idx);
    kB_gather_convw<<<1280, 256>>>(x, weight);
    dim3 grid(MAX_TILES, 2);
    gemm_mma_kernel<<<grid, 256, SM_TOTAL>>>(bias, out);
}

// round 10
// speedup vs baseline: 1.6451x; 1.4308x over previous
#include <cuda_runtime.h>
#include <cuda_fp16.h>
#include <cstdint>

#define B_SZ 8192
#define I_SZ 256
#define O_SZ 256
#define C_SZ 32
#define FULLMASK 0xFFFFFFFFu
#define MAX_TILES 96
#define PREP_NB 32

// ---------------- scratch (device globals; allocation-free) ----------------
__device__ int g_perm[B_SZ];
__device__ int g_offset[C_SZ];
__device__ int g_tiles[MAX_TILES];
__device__ int g_ntiles;
__device__ int g_is64;
__device__ int g_ok64[PREP_NB];
__device__ int g_bh64[PREP_NB * 32];     // per-block hists, both dtypes
__device__ int g_bh32[PREP_NB * 32];
__device__ __half g_wq[C_SZ * O_SZ * I_SZ];   // [c][o][i] fp16
__device__ __half g_xh[B_SZ * I_SZ];          // x fp16, UNPERMUTED

// ---- sense-reversing barrier among the 32 prep blocks (monotonic gen) -----
__device__ unsigned p_bcnt;
__device__ volatile unsigned p_bgen;

// ---------------------------------------------------------------------------
// k_prelude: blocks 0..31  : idx count -> barrier -> redundant prefix -> scatter
//            blocks 32..543: x fp32 -> fp16 (unpermuted)
//            blocks 544..799: conv_w  [O][I][C] f32 -> [C][O][I] f16
// ---------------------------------------------------------------------------
__global__ __launch_bounds__(256, 2)
void k_prelude(const float* __restrict__ x,
               const void* __restrict__ idx_ptr,
               const float* __restrict__ weight) {
    __shared__ char sbuf[17152];
    const int b = blockIdx.x;
    const int tid = threadIdx.x;

    if (b >= 32 && b < 544) {
        // ---------------- convert x (no smem) ----------------
        const int thr = (b - 32) * 256 + tid;      // 131072 threads
#pragma unroll
        for (int it = 0; it < 2; it++) {
            int g = thr + it * 131072;             // granule of 8 floats
            const float4* s = (const float4*)x + (size_t)g * 2;
            float4 v0 = s[0], v1 = s[1];
            union { uint4 u; __half2 h[4]; } P;
            P.h[0] = __float22half2_rn(make_float2(v0.x, v0.y));
            P.h[1] = __float22half2_rn(make_float2(v0.z, v0.w));
            P.h[2] = __float22half2_rn(make_float2(v1.x, v1.y));
            P.h[3] = __float22half2_rn(make_float2(v1.z, v1.w));
            ((uint4*)g_xh)[g] = P.u;
        }
        return;
    }

    if (b >= 544) {
        // ---------------- conv_w ----------------
        __half* sh = (__half*)sbuf;                // 256*33 fp16 = 16896 B
        const int o = b - 544;
        const float* src = weight + (size_t)o * (I_SZ * C_SZ);
        for (int l = tid; l < I_SZ * C_SZ; l += 256) {
            int i = l >> 5, c = l & 31;
            sh[i * 33 + c] = __float2half_rn(src[l]);
        }
        __syncthreads();
        for (int u = tid; u < (I_SZ * C_SZ) / 4; u += 256) {
            int c = u >> 6, i4 = u & 63;
            union { uint2 uu; __half h[4]; } H;
#pragma unroll
            for (int j = 0; j < 4; j++)
                H.h[j] = sh[(i4 * 4 + j) * 33 + c];
            size_t off = ((size_t)c << 16) + ((size_t)o << 8) + (size_t)i4 * 4;
            *(uint2*)(g_wq + off) = H.uu;
        }
        return;
    }

    // ======================= prep (blocks 0..31) ===========================
    int* s_h64 = (int*)sbuf;          // [8][32]
    int* s_h32 = s_h64 + 256;         // [8][32]
    int* s_wb  = s_h32 + 256;         // [8][32] per-warp scatter bases
    int* s_vote = s_wb + 256;         // [8]
    int* s_flag = s_vote + 8;         // [1] is64

    const int w = tid >> 5;
    const int lane = tid & 31;
    const int e = b * 256 + tid;

    if (w == 0 && lane < 8) s_vote[lane] = 0;
    s_h64[w * 32 + lane] = 0;
    s_h32[w * 32 + lane] = 0;
    __syncthreads();

    const int v32 = ((const int*)idx_ptr)[e];
    const int2 v64 = ((const int2*)idx_ptr)[e];

    {
        int ok64 = (v64.y == 0) && ((unsigned)v64.x < 32u);
        int allok = __all_sync(FULLMASK, ok64);
        if (lane == 0) s_vote[w] = allok;
    }
    {
        int c = v64.x & 31;
        unsigned m = __match_any_sync(FULLMASK, c);
        if (lane == (__ffs(m) - 1)) s_h64[w * 32 + c] += __popc(m);
    }
    {
        int c = v32 & 31;
        unsigned m = __match_any_sync(FULLMASK, c);
        if (lane == (__ffs(m) - 1)) s_h32[w * 32 + c] += __popc(m);
    }
    __syncthreads();

    // block hist (both dtypes) + vote to global
    if (tid < 32) {
        int t64 = 0, t32 = 0;
#pragma unroll
        for (int w2 = 0; w2 < 8; w2++) {
            t64 += s_h64[w2 * 32 + tid];
            t32 += s_h32[w2 * 32 + tid];
        }
        g_bh64[b * 32 + tid] = t64;
        g_bh32[b * 32 + tid] = t32;
        if (tid == 0) {
            int a = 1;
#pragma unroll
            for (int i = 0; i < 8; i++) a &= s_vote[i];
            g_ok64[b] = a;
        }
    }

    // ---- single 32-block barrier ----
    __syncthreads();
    if (tid == 0) {
        unsigned my = p_bgen;
        __threadfence();
        if (atomicAdd(&p_bcnt, 1u) == PREP_NB - 1) {
            p_bcnt = 0;
            __threadfence();
            p_bgen = my + 1;
        } else {
            while (p_bgen == my) {}
            __threadfence();
        }
    }
    __syncthreads();

    // ---- redundant prefix: every block computes its own cursors ----
    if (tid < 32) {
        int v = g_ok64[tid];
        v = __all_sync(FULLMASK, v);
        if (tid == 0) s_flag[0] = v;
    }
    __syncthreads();
    const int is64 = s_flag[0];
    const int* BH = is64 ? g_bh64 : g_bh32;
    int* s_hsel = is64 ? s_h64 : s_h32;

    if (tid < 32) {
        const int c = tid;
        int tot = 0, before = 0;
#pragma unroll
        for (int b2 = 0; b2 < PREP_NB; b2++) {
            int h = BH[b2 * 32 + c];
            if (b2 < b) before += h;
            tot += h;
        }
        // exclusive channel offsets via shuffle scan of tot
        int incl = tot;
#pragma unroll
        for (int d = 1; d < 32; d <<= 1) {
            int u = __shfl_up_sync(FULLMASK, incl, d);
            if (lane >= d) incl += u;
        }
        int off = incl - tot;
        // per-warp bases within this block
        int run = off + before;
#pragma unroll
        for (int w2 = 0; w2 < 8; w2++) {
            s_wb[w2 * 32 + c] = run;
            run += s_hsel[w2 * 32 + c];
        }
        if (b == 0) {
            g_offset[c] = off;
            if (c == 0) g_is64 = is64;
        }
        // block 0 thread 0 emits tiles (needs all tots -> via shfl gather)
        if (b == 0) {
            // broadcast tots to lane 0 one at a time
            int nt_local = 0;
            if (lane == 0) {
                // lane0 cannot see others' tot directly; rebuild from BH
                int nt = 0;
                for (int cc = 0; cc < 32; cc++) {
                    int cnt = 0;
                    for (int b2 = 0; b2 < PREP_NB; b2++) cnt += BH[b2 * 32 + cc];
                    for (int m = 0; m * 128 < cnt; m++) {
                        int rows = min(128, cnt - m * 128);
                        g_tiles[nt++] = cc | (m << 8) | (rows << 16);
                    }
                }
                g_ntiles = nt;
            }
            (void)nt_local;
        }
    }
    __syncthreads();

    // ---- scatter ----
    {
        int c = is64 ? (v64.x & 31) : (v32 & 31);
        unsigned m = __match_any_sync(FULLMASK, c);
        int rank = __popc(m & ((1u << lane) - 1u));
        int base = s_wb[w * 32 + c];
        g_perm[base + rank] = e;
    }
}

// ---------------------------------------------------------------------------
// GEMM: 128x128xK256, cp.async 3-stage pipeline; A rows gathered from g_xh.
// ---------------------------------------------------------------------------
#define RB 144
#define A_CH (128 * RB)
#define STAGE (2 * A_CH)
#define OFF_ROW  0
#define OFF_BIAS 512
#define OFF_PIPE 1024
#define SM_TOTAL (OFF_PIPE + 3 * STAGE)   // 111616

__device__ __forceinline__ uint32_t smem_u32(const void* p) {
    uint32_t a;
    asm("{ .reg .u64 t; cvta.to.shared.u64 t, %1; cvt.u32.u64 %0, t; }"
        : "=r"(a) : "l"(p));
    return a;
}

#define CP16(dst, src) \
    asm volatile("cp.async.cg.shared.global [%0], [%1], 16;" \
                 :: "r"(dst), "l"(src) : "memory")
#define CP_COMMIT() asm volatile("cp.async.commit_group;" ::: "memory")
#define CP_WAIT(n)  asm volatile("cp.async.wait_group %0;" :: "n"(n) : "memory")

#define LDSM_X4(r0, r1, r2, r3, addr)                                       \
    asm volatile("ldmatrix.sync.aligned.m8n8.x4.shared.b16 "                \
                 "{%0,%1,%2,%3}, [%4];"                                     \
                 : "=r"(r0), "=r"(r1), "=r"(r2), "=r"(r3) : "r"(addr))

#define MMA16816(d0, d1, d2, d3, a0, a1, a2, a3, b0, b1)                    \
    asm volatile("mma.sync.aligned.m16n8k16.row.col.f32.f16.f16.f32 "       \
                 "{%0,%1,%2,%3}, {%4,%5,%6,%7}, {%8,%9}, {%0,%1,%2,%3};"    \
                 : "+f"(d0), "+f"(d1), "+f"(d2), "+f"(d3)                   \
                 : "r"(a0), "r"(a1), "r"(a2), "r"(a3), "r"(b0), "r"(b1))

__global__ __launch_bounds__(256, 2)
void gemm_mma_kernel(const float* __restrict__ bias, float* __restrict__ out) {
    extern __shared__ char smem[];
    if ((int)blockIdx.x >= g_ntiles) return;
    const int t = g_tiles[blockIdx.x];
    const int c = t & 31;
    const int m0 = ((t >> 8) & 0xFF) * 128;
    const int rows = (t >> 16) & 0xFF;
    const int base = g_offset[c] + m0;
    const int n0 = blockIdx.y * 128;

    const int tid = threadIdx.x;
    const int wid = tid >> 5;
    const int lane = tid & 31;
    const int wm = wid >> 2;
    const int wn = wid & 3;

    int* s_row = (int*)(smem + OFF_ROW);
    float* s_bias = (float*)(smem + OFF_BIAS);
    const uint32_t sb = smem_u32(smem);

    if (tid < 128) {
        s_row[tid] = g_perm[base + min(tid, rows - 1)];
        s_bias[tid] = bias[(size_t)(n0 + tid) * C_SZ + c];
    }
    __syncthreads();   // fills below read s_row

    const __half* wsrc0 = g_wq + ((size_t)c << 16) + (size_t)n0 * I_SZ;

    auto fill = [&](int kc, int stage) {
        const uint32_t dstA = sb + OFF_PIPE + stage * STAGE;
        const uint32_t dstW = dstA + A_CH;
        const int ko = kc * 64;
#pragma unroll
        for (int it = 0; it < 4; it++) {
            int task = tid + it * 256;
            int r = task >> 3, g = task & 7;
            const __half* src = g_xh + (size_t)s_row[r] * I_SZ + ko + g * 8;
            CP16(dstA + r * RB + g * 16, src);
        }
        const __half* sw = wsrc0 + ko;
#pragma unroll
        for (int it = 0; it < 4; it++) {
            int task = tid + it * 256;
            int r = task >> 3, g = task & 7;
            CP16(dstW + r * RB + g * 16, sw + (size_t)r * I_SZ + g * 8);
        }
        CP_COMMIT();
    };

    fill(0, 0);
    fill(1, 1);
    fill(2, 2);

    float acc[4][4][4];
#pragma unroll
    for (int i = 0; i < 4; i++)
#pragma unroll
        for (int j = 0; j < 4; j++)
#pragma unroll
            for (int q = 0; q < 4; q++) acc[i][j][q] = 0.0f;

    uint32_t aoff[4], boff[2];
#pragma unroll
    for (int mt = 0; mt < 4; mt++)
        aoff[mt] = (wm * 64 + mt * 16 + (lane & 15)) * RB + (lane >> 4) * 16;
#pragma unroll
    for (int p = 0; p < 2; p++)
        boff[p] = (wn * 32 + p * 16 + (lane >> 4) * 8 + (lane & 7)) * RB +
                  ((lane >> 3) & 1) * 16;

    auto compute = [&](int stage) {
        const uint32_t ab = sb + OFF_PIPE + stage * STAGE;
        const uint32_t wb = ab + A_CH;
#pragma unroll
        for (int j = 0; j < 4; j++) {
            const uint32_t kb = j * 32;
            uint32_t a[4][4], b[2][4];
#pragma unroll
            for (int mt = 0; mt < 4; mt++)
                LDSM_X4(a[mt][0], a[mt][1], a[mt][2], a[mt][3],
                        ab + aoff[mt] + kb);
#pragma unroll
            for (int p = 0; p < 2; p++)
                LDSM_X4(b[p][0], b[p][1], b[p][2], b[p][3],
                        wb + boff[p] + kb);
#pragma unroll
            for (int mt = 0; mt < 4; mt++) {
#pragma unroll
                for (int nt = 0; nt < 4; nt++) {
                    uint32_t b0 = b[nt >> 1][(nt & 1) * 2 + 0];
                    uint32_t b1 = b[nt >> 1][(nt & 1) * 2 + 1];
                    MMA16816(acc[mt][nt][0], acc[mt][nt][1],
                             acc[mt][nt][2], acc[mt][nt][3],
                             a[mt][0], a[mt][1], a[mt][2], a[mt][3], b0, b1);
                }
            }
        }
    };

    CP_WAIT(2);
    __syncthreads();
    compute(0);
    __syncthreads();
    fill(3, 0);
    CP_WAIT(2);
    __syncthreads();
    compute(1);
    CP_WAIT(1);
    __syncthreads();
    compute(2);
    CP_WAIT(0);
    __syncthreads();
    compute(0);

    const int g = lane >> 2, tq = lane & 3;
#pragma unroll
    for (int mt = 0; mt < 4; mt++) {
        int rl = wm * 64 + mt * 16 + g;
#pragma unroll
        for (int h = 0; h < 2; h++) {
            int rr = rl + h * 8;
            if (rr < rows) {
                float* op = out + (size_t)s_row[rr] * O_SZ + n0;
#pragma unroll
                for (int nt = 0; nt < 4; nt++) {
                    int cl = wn * 32 + nt * 8 + 2 * tq;
                    float2 v;
                    v.x = acc[mt][nt][h * 2 + 0] + s_bias[cl + 0];
                    v.y = acc[mt][nt][h * 2 + 1] + s_bias[cl + 1];
                    *(float2*)(op + cl) = v;
                }
            }
        }
    }
}

// ---------------------------------------------------------------------------
// launch: 2 kernels
// ---------------------------------------------------------------------------
extern "C" void kernel_launch(void* const* d_in, const int* in_sizes, int n_in,
                              void* d_out, int out_size) {
    const float* x      = (const float*)d_in[0];
    const void*  idx    = d_in[1];
    const float* weight = (const float*)d_in[2];
    const float* bias   = (const float*)d_in[3];
    float* out = (float*)d_out;

    cudaFuncSetAttribute(gemm_mma_kernel,
                         cudaFuncAttributeMaxDynamicSharedMemorySize, SM_TOTAL);

    k_prelude<<<800, 256>>>(x, idx, weight);
    dim3 grid(MAX_TILES, 2);
    gemm_mma_kernel<<<grid, 256, SM_TOTAL>>>(bias, out);
}

// round 11
// speedup vs baseline: 1.7220x; 1.0467x over previous
#include <cuda_runtime.h>
#include <cuda_fp16.h>
#include <cstdint>

#define B_SZ 8192
#define I_SZ 256
#define O_SZ 256
#define C_SZ 32
#define FULLMASK 0xFFFFFFFFu
#define MAX_TILES 96
#define PREP_NB 32

// ---------------- scratch (device globals; allocation-free) ----------------
__device__ int g_perm[B_SZ];
__device__ int g_offset[C_SZ];
__device__ int g_tiles[MAX_TILES];
__device__ int g_ntiles;
__device__ int g_is64;
__device__ int g_ok64[PREP_NB];
__device__ int g_bh64[PREP_NB * 32];
__device__ int g_bh32[PREP_NB * 32];
__device__ __half g_wq[C_SZ * O_SZ * I_SZ];   // [c][o][i] fp16
__device__ __half g_xh[B_SZ * I_SZ];          // x fp16, UNPERMUTED

__device__ unsigned p_bcnt;
__device__ volatile unsigned p_bgen;

// ---------------------------------------------------------------------------
// k_prelude: blocks 0..31 idx sort; 32..543 convert x; 544..799 conv_w
// ---------------------------------------------------------------------------
__global__ __launch_bounds__(256, 2)
void k_prelude(const float* __restrict__ x,
               const void* __restrict__ idx_ptr,
               const float* __restrict__ weight) {
    __shared__ char sbuf[17152];
    const int b = blockIdx.x;
    const int tid = threadIdx.x;

    if (b >= 32 && b < 544) {
        const int thr = (b - 32) * 256 + tid;
#pragma unroll
        for (int it = 0; it < 2; it++) {
            int g = thr + it * 131072;
            const float4* s = (const float4*)x + (size_t)g * 2;
            float4 v0 = s[0], v1 = s[1];
            union { uint4 u; __half2 h[4]; } P;
            P.h[0] = __float22half2_rn(make_float2(v0.x, v0.y));
            P.h[1] = __float22half2_rn(make_float2(v0.z, v0.w));
            P.h[2] = __float22half2_rn(make_float2(v1.x, v1.y));
            P.h[3] = __float22half2_rn(make_float2(v1.z, v1.w));
            ((uint4*)g_xh)[g] = P.u;
        }
        return;
    }

    if (b >= 544) {
        __half* sh = (__half*)sbuf;
        const int o = b - 544;
        const float* src = weight + (size_t)o * (I_SZ * C_SZ);
        for (int l = tid; l < I_SZ * C_SZ; l += 256) {
            int i = l >> 5, c = l & 31;
            sh[i * 33 + c] = __float2half_rn(src[l]);
        }
        __syncthreads();
        for (int u = tid; u < (I_SZ * C_SZ) / 4; u += 256) {
            int c = u >> 6, i4 = u & 63;
            union { uint2 uu; __half h[4]; } H;
#pragma unroll
            for (int j = 0; j < 4; j++)
                H.h[j] = sh[(i4 * 4 + j) * 33 + c];
            size_t off = ((size_t)c << 16) + ((size_t)o << 8) + (size_t)i4 * 4;
            *(uint2*)(g_wq + off) = H.uu;
        }
        return;
    }

    // ======================= prep (blocks 0..31) ===========================
    int* s_h64 = (int*)sbuf;
    int* s_h32 = s_h64 + 256;
    int* s_wb  = s_h32 + 256;
    int* s_vote = s_wb + 256;
    int* s_flag = s_vote + 8;

    const int w = tid >> 5;
    const int lane = tid & 31;
    const int e = b * 256 + tid;

    if (w == 0 && lane < 8) s_vote[lane] = 0;
    s_h64[w * 32 + lane] = 0;
    s_h32[w * 32 + lane] = 0;
    __syncthreads();

    const int v32 = ((const int*)idx_ptr)[e];
    const int2 v64 = ((const int2*)idx_ptr)[e];

    {
        int ok64 = (v64.y == 0) && ((unsigned)v64.x < 32u);
        int allok = __all_sync(FULLMASK, ok64);
        if (lane == 0) s_vote[w] = allok;
    }
    {
        int c = v64.x & 31;
        unsigned m = __match_any_sync(FULLMASK, c);
        if (lane == (__ffs(m) - 1)) s_h64[w * 32 + c] += __popc(m);
    }
    {
        int c = v32 & 31;
        unsigned m = __match_any_sync(FULLMASK, c);
        if (lane == (__ffs(m) - 1)) s_h32[w * 32 + c] += __popc(m);
    }
    __syncthreads();

    if (tid < 32) {
        int t64 = 0, t32 = 0;
#pragma unroll
        for (int w2 = 0; w2 < 8; w2++) {
            t64 += s_h64[w2 * 32 + tid];
            t32 += s_h32[w2 * 32 + tid];
        }
        g_bh64[b * 32 + tid] = t64;
        g_bh32[b * 32 + tid] = t32;
        if (tid == 0) {
            int a = 1;
#pragma unroll
            for (int i = 0; i < 8; i++) a &= s_vote[i];
            g_ok64[b] = a;
        }
    }

    __syncthreads();
    if (tid == 0) {
        unsigned my = p_bgen;
        __threadfence();
        if (atomicAdd(&p_bcnt, 1u) == PREP_NB - 1) {
            p_bcnt = 0;
            __threadfence();
            p_bgen = my + 1;
        } else {
            while (p_bgen == my) {}
            __threadfence();
        }
    }
    __syncthreads();

    if (tid < 32) {
        int v = g_ok64[tid];
        v = __all_sync(FULLMASK, v);
        if (tid == 0) s_flag[0] = v;
    }
    __syncthreads();
    const int is64 = s_flag[0];
    const int* BH = is64 ? g_bh64 : g_bh32;
    int* s_hsel = is64 ? s_h64 : s_h32;

    if (tid < 32) {
        const int c = tid;
        int tot = 0, before = 0;
#pragma unroll
        for (int b2 = 0; b2 < PREP_NB; b2++) {
            int h = BH[b2 * 32 + c];
            if (b2 < b) before += h;
            tot += h;
        }
        int incl = tot;
#pragma unroll
        for (int d = 1; d < 32; d <<= 1) {
            int u = __shfl_up_sync(FULLMASK, incl, d);
            if (lane >= d) incl += u;
        }
        int off = incl - tot;
        int run = off + before;
#pragma unroll
        for (int w2 = 0; w2 < 8; w2++) {
            s_wb[w2 * 32 + c] = run;
            run += s_hsel[w2 * 32 + c];
        }
        if (b == 0) {
            g_offset[c] = off;
            if (c == 0) g_is64 = is64;
            if (lane == 0) {
                int nt = 0;
                for (int cc = 0; cc < 32; cc++) {
                    int cnt = 0;
                    for (int b2 = 0; b2 < PREP_NB; b2++) cnt += BH[b2 * 32 + cc];
                    for (int m = 0; m * 128 < cnt; m++) {
                        int rows = min(128, cnt - m * 128);
                        g_tiles[nt++] = cc | (m << 8) | (rows << 16);
                    }
                }
                g_ntiles = nt;
            }
        }
    }
    __syncthreads();

    {
        int c = is64 ? (v64.x & 31) : (v32 & 31);
        unsigned m = __match_any_sync(FULLMASK, c);
        int rank = __popc(m & ((1u << lane) - 1u));
        int base = s_wb[w * 32 + c];
        g_perm[base + rank] = e;
    }
}

// ---------------------------------------------------------------------------
// GEMM: 128x128xK256, cp.async 3-stage, SWIZZLED 128B rows -> 2 CTAs/SM.
// swizzled granule: addr = row*128 + ((g ^ (row&7)) << 4), g in [0,8)
// ---------------------------------------------------------------------------
#define RB 128
#define A_CH (128 * RB)                  // 16384
#define STAGE (2 * A_CH)                 // 32768
#define OFF_ROW  0
#define OFF_BIAS 512
#define OFF_PIPE 1024
#define SM_TOTAL (OFF_PIPE + 3 * STAGE)  // 99328

__device__ __forceinline__ uint32_t smem_u32(const void* p) {
    uint32_t a;
    asm("{ .reg .u64 t; cvta.to.shared.u64 t, %1; cvt.u32.u64 %0, t; }"
        : "=r"(a) : "l"(p));
    return a;
}

#define CP16(dst, src) \
    asm volatile("cp.async.cg.shared.global [%0], [%1], 16;" \
                 :: "r"(dst), "l"(src) : "memory")
#define CP_COMMIT() asm volatile("cp.async.commit_group;" ::: "memory")
#define CP_WAIT(n)  asm volatile("cp.async.wait_group %0;" :: "n"(n) : "memory")

#define LDSM_X4(r0, r1, r2, r3, addr)                                       \
    asm volatile("ldmatrix.sync.aligned.m8n8.x4.shared.b16 "                \
                 "{%0,%1,%2,%3}, [%4];"                                     \
                 : "=r"(r0), "=r"(r1), "=r"(r2), "=r"(r3) : "r"(addr))

#define MMA16816(d0, d1, d2, d3, a0, a1, a2, a3, b0, b1)                    \
    asm volatile("mma.sync.aligned.m16n8k16.row.col.f32.f16.f16.f32 "       \
                 "{%0,%1,%2,%3}, {%4,%5,%6,%7}, {%8,%9}, {%0,%1,%2,%3};"    \
                 : "+f"(d0), "+f"(d1), "+f"(d2), "+f"(d3)                   \
                 : "r"(a0), "r"(a1), "r"(a2), "r"(a3), "r"(b0), "r"(b1))

__global__ __launch_bounds__(256, 2)
void gemm_mma_kernel(const float* __restrict__ bias, float* __restrict__ out) {
    extern __shared__ char smem[];
    if ((int)blockIdx.x >= g_ntiles) return;
    const int t = g_tiles[blockIdx.x];
    const int c = t & 31;
    const int m0 = ((t >> 8) & 0xFF) * 128;
    const int rows = (t >> 16) & 0xFF;
    const int base = g_offset[c] + m0;
    const int n0 = blockIdx.y * 128;

    const int tid = threadIdx.x;
    const int wid = tid >> 5;
    const int lane = tid & 31;
    const int wm = wid >> 2;
    const int wn = wid & 3;

    int* s_row = (int*)(smem + OFF_ROW);
    float* s_bias = (float*)(smem + OFF_BIAS);
    const uint32_t sb = smem_u32(smem);

    if (tid < 128) {
        s_row[tid] = g_perm[base + min(tid, rows - 1)];
        s_bias[tid] = bias[(size_t)(n0 + tid) * C_SZ + c];
    }
    __syncthreads();

    const __half* wsrc0 = g_wq + ((size_t)c << 16) + (size_t)n0 * I_SZ;

    auto fill = [&](int kc, int stage) {
        const uint32_t dstA = sb + OFF_PIPE + stage * STAGE;
        const uint32_t dstW = dstA + A_CH;
        const int ko = kc * 64;
#pragma unroll
        for (int it = 0; it < 4; it++) {
            int task = tid + it * 256;
            int r = task >> 3, g = task & 7;
            uint32_t soff = r * RB + ((g ^ (r & 7)) << 4);
            const __half* src = g_xh + (size_t)s_row[r] * I_SZ + ko + g * 8;
            CP16(dstA + soff, src);
        }
        const __half* sw = wsrc0 + ko;
#pragma unroll
        for (int it = 0; it < 4; it++) {
            int task = tid + it * 256;
            int r = task >> 3, g = task & 7;
            uint32_t soff = r * RB + ((g ^ (r & 7)) << 4);
            CP16(dstW + soff, sw + (size_t)r * I_SZ + g * 8);
        }
        CP_COMMIT();
    };

    fill(0, 0);
    fill(1, 1);
    fill(2, 2);

    float acc[4][4][4];
#pragma unroll
    for (int i = 0; i < 4; i++)
#pragma unroll
        for (int j = 0; j < 4; j++)
#pragma unroll
            for (int q = 0; q < 4; q++) acc[i][j][q] = 0.0f;

    // A: row ra = wm*64+mt*16+(lane&15), granule = j*2 + (lane>>4)
    // B: row rb = wn*32+p*16+(lane>>4)*8+(lane&7), granule = j*2 + ((lane>>3)&1)
    uint32_t arow[4], brow[2];
    const int ahi = lane >> 4;             // granule low bit for A
    const int bhi = (lane >> 3) & 1;       // granule low bit for B
#pragma unroll
    for (int mt = 0; mt < 4; mt++)
        arow[mt] = wm * 64 + mt * 16 + (lane & 15);
#pragma unroll
    for (int p = 0; p < 2; p++)
        brow[p] = wn * 32 + p * 16 + (lane >> 4) * 8 + (lane & 7);

    auto compute = [&](int stage) {
        const uint32_t ab = sb + OFF_PIPE + stage * STAGE;
        const uint32_t wb = ab + A_CH;
#pragma unroll
        for (int j = 0; j < 4; j++) {
            uint32_t a[4][4], b[2][4];
#pragma unroll
            for (int mt = 0; mt < 4; mt++) {
                uint32_t g = (uint32_t)(j * 2 + ahi);
                uint32_t addr = ab + arow[mt] * RB +
                                ((g ^ (arow[mt] & 7)) << 4);
                LDSM_X4(a[mt][0], a[mt][1], a[mt][2], a[mt][3], addr);
            }
#pragma unroll
            for (int p = 0; p < 2; p++) {
                uint32_t g = (uint32_t)(j * 2 + bhi);
                uint32_t addr = wb + brow[p] * RB +
                                ((g ^ (brow[p] & 7)) << 4);
                LDSM_X4(b[p][0], b[p][1], b[p][2], b[p][3], addr);
            }
#pragma unroll
            for (int mt = 0; mt < 4; mt++) {
#pragma unroll
                for (int nt = 0; nt < 4; nt++) {
                    uint32_t b0 = b[nt >> 1][(nt & 1) * 2 + 0];
                    uint32_t b1 = b[nt >> 1][(nt & 1) * 2 + 1];
                    MMA16816(acc[mt][nt][0], acc[mt][nt][1],
                             acc[mt][nt][2], acc[mt][nt][3],
                             a[mt][0], a[mt][1], a[mt][2], a[mt][3], b0, b1);
                }
            }
        }
    };

    CP_WAIT(2);
    __syncthreads();
    compute(0);
    __syncthreads();
    fill(3, 0);
    CP_WAIT(2);
    __syncthreads();
    compute(1);
    CP_WAIT(1);
    __syncthreads();
    compute(2);
    CP_WAIT(0);
    __syncthreads();
    compute(0);

    const int g = lane >> 2, tq = lane & 3;
#pragma unroll
    for (int mt = 0; mt < 4; mt++) {
        int rl = wm * 64 + mt * 16 + g;
#pragma unroll
        for (int h = 0; h < 2; h++) {
            int rr = rl + h * 8;
            if (rr < rows) {
                float* op = out + (size_t)s_row[rr] * O_SZ + n0;
#pragma unroll
                for (int nt = 0; nt < 4; nt++) {
                    int cl = wn * 32 + nt * 8 + 2 * tq;
                    float2 v;
                    v.x = acc[mt][nt][h * 2 + 0] + s_bias[cl + 0];
                    v.y = acc[mt][nt][h * 2 + 1] + s_bias[cl + 1];
                    *(float2*)(op + cl) = v;
                }
            }
        }
    }
}

// ---------------------------------------------------------------------------
// launch: 2 kernels
// ---------------------------------------------------------------------------
extern "C" void kernel_launch(void* const* d_in, const int* in_sizes, int n_in,
                              void* d_out, int out_size) {
    const float* x      = (const float*)d_in[0];
    const void*  idx    = d_in[1];
    const float* weight = (const float*)d_in[2];
    const float* bias   = (const float*)d_in[3];
    float* out = (float*)d_out;

    cudaFuncSetAttribute(gemm_mma_kernel,
                         cudaFuncAttributeMaxDynamicSharedMemorySize, SM_TOTAL);

    k_prelude<<<800, 256>>>(x, idx, weight);
    dim3 grid(MAX_TILES, 2);
    gemm_mma_kernel<<<grid, 256, SM_TOTAL>>>(bias, out);
}

// round 12
// speedup vs baseline: 1.8825x; 1.0932x over previous
#include <cuda_runtime.h>
#include <cuda_fp16.h>
#include <cstdint>

#define B_SZ 8192
#define I_SZ 256
#define O_SZ 256
#define C_SZ 32
#define FULLMASK 0xFFFFFFFFu
#define MAX_TILES 160
#define TILE_M 64
#define PREP_NB 32

// ---------------- scratch (device globals; allocation-free) ----------------
__device__ int g_perm[B_SZ];
__device__ int g_offset[C_SZ];
__device__ int g_tiles[MAX_TILES];
__device__ int g_ntiles;
__device__ int g_is64;
__device__ int g_ok64[PREP_NB];
__device__ int g_bh64[PREP_NB * 32];
__device__ int g_bh32[PREP_NB * 32];
__device__ __half g_wq[C_SZ * O_SZ * I_SZ];   // [c][o][i] fp16
__device__ __half g_xh[B_SZ * I_SZ];          // x fp16, UNPERMUTED

__device__ unsigned p_bcnt;
__device__ volatile unsigned p_bgen;

// ---------------------------------------------------------------------------
// k_prelude: blocks 0..31 idx sort; 32..543 convert x; 544..799 conv_w
// ---------------------------------------------------------------------------
__global__ __launch_bounds__(256, 2)
void k_prelude(const float* __restrict__ x,
               const void* __restrict__ idx_ptr,
               const float* __restrict__ weight) {
    __shared__ char sbuf[17152];
    const int b = blockIdx.x;
    const int tid = threadIdx.x;

    if (b >= 32 && b < 544) {
        const int thr = (b - 32) * 256 + tid;
#pragma unroll
        for (int it = 0; it < 2; it++) {
            int g = thr + it * 131072;
            const float4* s = (const float4*)x + (size_t)g * 2;
            float4 v0 = s[0], v1 = s[1];
            union { uint4 u; __half2 h[4]; } P;
            P.h[0] = __float22half2_rn(make_float2(v0.x, v0.y));
            P.h[1] = __float22half2_rn(make_float2(v0.z, v0.w));
            P.h[2] = __float22half2_rn(make_float2(v1.x, v1.y));
            P.h[3] = __float22half2_rn(make_float2(v1.z, v1.w));
            ((uint4*)g_xh)[g] = P.u;
        }
        return;
    }

    if (b >= 544) {
        __half* sh = (__half*)sbuf;
        const int o = b - 544;
        const float* src = weight + (size_t)o * (I_SZ * C_SZ);
        for (int l = tid; l < I_SZ * C_SZ; l += 256) {
            int i = l >> 5, c = l & 31;
            sh[i * 33 + c] = __float2half_rn(src[l]);
        }
        __syncthreads();
        for (int u = tid; u < (I_SZ * C_SZ) / 4; u += 256) {
            int c = u >> 6, i4 = u & 63;
            union { uint2 uu; __half h[4]; } H;
#pragma unroll
            for (int j = 0; j < 4; j++)
                H.h[j] = sh[(i4 * 4 + j) * 33 + c];
            size_t off = ((size_t)c << 16) + ((size_t)o << 8) + (size_t)i4 * 4;
            *(uint2*)(g_wq + off) = H.uu;
        }
        return;
    }

    // ======================= prep (blocks 0..31) ===========================
    int* s_h64 = (int*)sbuf;
    int* s_h32 = s_h64 + 256;
    int* s_wb  = s_h32 + 256;
    int* s_vote = s_wb + 256;
    int* s_flag = s_vote + 8;

    const int w = tid >> 5;
    const int lane = tid & 31;
    const int e = b * 256 + tid;

    if (w == 0 && lane < 8) s_vote[lane] = 0;
    s_h64[w * 32 + lane] = 0;
    s_h32[w * 32 + lane] = 0;
    __syncthreads();

    const int v32 = ((const int*)idx_ptr)[e];
    const int2 v64 = ((const int2*)idx_ptr)[e];

    {
        int ok64 = (v64.y == 0) && ((unsigned)v64.x < 32u);
        int allok = __all_sync(FULLMASK, ok64);
        if (lane == 0) s_vote[w] = allok;
    }
    {
        int c = v64.x & 31;
        unsigned m = __match_any_sync(FULLMASK, c);
        if (lane == (__ffs(m) - 1)) s_h64[w * 32 + c] += __popc(m);
    }
    {
        int c = v32 & 31;
        unsigned m = __match_any_sync(FULLMASK, c);
        if (lane == (__ffs(m) - 1)) s_h32[w * 32 + c] += __popc(m);
    }
    __syncthreads();

    if (tid < 32) {
        int t64 = 0, t32 = 0;
#pragma unroll
        for (int w2 = 0; w2 < 8; w2++) {
            t64 += s_h64[w2 * 32 + tid];
            t32 += s_h32[w2 * 32 + tid];
        }
        g_bh64[b * 32 + tid] = t64;
        g_bh32[b * 32 + tid] = t32;
        if (tid == 0) {
            int a = 1;
#pragma unroll
            for (int i = 0; i < 8; i++) a &= s_vote[i];
            g_ok64[b] = a;
        }
    }

    __syncthreads();
    if (tid == 0) {
        unsigned my = p_bgen;
        __threadfence();
        if (atomicAdd(&p_bcnt, 1u) == PREP_NB - 1) {
            p_bcnt = 0;
            __threadfence();
            p_bgen = my + 1;
        } else {
            while (p_bgen == my) {}
            __threadfence();
        }
    }
    __syncthreads();

    if (tid < 32) {
        int v = g_ok64[tid];
        v = __all_sync(FULLMASK, v);
        if (tid == 0) s_flag[0] = v;
    }
    __syncthreads();
    const int is64 = s_flag[0];
    const int* BH = is64 ? g_bh64 : g_bh32;
    int* s_hsel = is64 ? s_h64 : s_h32;

    if (tid < 32) {
        const int c = tid;
        int tot = 0, before = 0;
#pragma unroll
        for (int b2 = 0; b2 < PREP_NB; b2++) {
            int h = BH[b2 * 32 + c];
            if (b2 < b) before += h;
            tot += h;
        }
        int incl = tot;
#pragma unroll
        for (int d = 1; d < 32; d <<= 1) {
            int u = __shfl_up_sync(FULLMASK, incl, d);
            if (lane >= d) incl += u;
        }
        int off = incl - tot;
        int run = off + before;
#pragma unroll
        for (int w2 = 0; w2 < 8; w2++) {
            s_wb[w2 * 32 + c] = run;
            run += s_hsel[w2 * 32 + c];
        }
        if (b == 0) {
            g_offset[c] = off;
            if (c == 0) g_is64 = is64;
            if (lane == 0) {
                int nt = 0;
                for (int cc = 0; cc < 32; cc++) {
                    int cnt = 0;
                    for (int b2 = 0; b2 < PREP_NB; b2++) cnt += BH[b2 * 32 + cc];
                    for (int m = 0; m * TILE_M < cnt; m++) {
                        int rows = min(TILE_M, cnt - m * TILE_M);
                        g_tiles[nt++] = cc | (m << 8) | (rows << 16);
                    }
                }
                g_ntiles = nt;
            }
        }
    }
    __syncthreads();

    {
        int c = is64 ? (v64.x & 31) : (v32 & 31);
        unsigned m = __match_any_sync(FULLMASK, c);
        int rank = __popc(m & ((1u << lane) - 1u));
        int base = s_wb[w * 32 + c];
        g_perm[base + rank] = e;
    }
}

// ---------------------------------------------------------------------------
// GEMM: 64x128xK256 tiles, cp.async 3-stage, swizzled 128B rows, 3 CTAs/SM.
// ---------------------------------------------------------------------------
#define RB 128
#define A_CH (TILE_M * RB)               // 8192
#define W_CH (128 * RB)                  // 16384
#define STAGE (A_CH + W_CH)              // 24576
#define OFF_ROW  0                       // 64 ints = 256 B
#define OFF_BIAS 256                     // 128 floats = 512 B
#define OFF_PIPE 768
#define SM_TOTAL (OFF_PIPE + 3 * STAGE)  // 74496

__device__ __forceinline__ uint32_t smem_u32(const void* p) {
    uint32_t a;
    asm("{ .reg .u64 t; cvta.to.shared.u64 t, %1; cvt.u32.u64 %0, t; }"
        : "=r"(a) : "l"(p));
    return a;
}

#define CP16(dst, src) \
    asm volatile("cp.async.cg.shared.global [%0], [%1], 16;" \
                 :: "r"(dst), "l"(src) : "memory")
#define CP_COMMIT() asm volatile("cp.async.commit_group;" ::: "memory")
#define CP_WAIT(n)  asm volatile("cp.async.wait_group %0;" :: "n"(n) : "memory")

#define LDSM_X4(r0, r1, r2, r3, addr)                                       \
    asm volatile("ldmatrix.sync.aligned.m8n8.x4.shared.b16 "                \
                 "{%0,%1,%2,%3}, [%4];"                                     \
                 : "=r"(r0), "=r"(r1), "=r"(r2), "=r"(r3) : "r"(addr))

#define MMA16816(d0, d1, d2, d3, a0, a1, a2, a3, b0, b1)                    \
    asm volatile("mma.sync.aligned.m16n8k16.row.col.f32.f16.f16.f32 "       \
                 "{%0,%1,%2,%3}, {%4,%5,%6,%7}, {%8,%9}, {%0,%1,%2,%3};"    \
                 : "+f"(d0), "+f"(d1), "+f"(d2), "+f"(d3)                   \
                 : "r"(a0), "r"(a1), "r"(a2), "r"(a3), "r"(b0), "r"(b1))

__global__ __launch_bounds__(256, 3)
void gemm_mma_kernel(const float* __restrict__ bias, float* __restrict__ out) {
    extern __shared__ char smem[];
    if ((int)blockIdx.x >= g_ntiles) return;
    const int t = g_tiles[blockIdx.x];
    const int c = t & 31;
    const int m0 = ((t >> 8) & 0xFF) * TILE_M;
    const int rows = (t >> 16) & 0xFF;
    const int base = g_offset[c] + m0;
    const int n0 = blockIdx.y * 128;

    const int tid = threadIdx.x;
    const int wid = tid >> 5;
    const int lane = tid & 31;
    const int wm = wid >> 2;      // 0..1, 32 rows each
    const int wn = wid & 3;       // 0..3, 32 cols each

    int* s_row = (int*)(smem + OFF_ROW);
    float* s_bias = (float*)(smem + OFF_BIAS);
    const uint32_t sb = smem_u32(smem);

    if (tid < TILE_M) s_row[tid] = g_perm[base + min(tid, rows - 1)];
    if (tid < 128) s_bias[tid] = bias[(size_t)(n0 + tid) * C_SZ + c];
    __syncthreads();

    const __half* wsrc0 = g_wq + ((size_t)c << 16) + (size_t)n0 * I_SZ;

    auto fill = [&](int kc, int stage) {
        const uint32_t dstA = sb + OFF_PIPE + stage * STAGE;
        const uint32_t dstW = dstA + A_CH;
        const int ko = kc * 64;
        // A: 64 rows x 8 granules = 512 tasks
#pragma unroll
        for (int it = 0; it < 2; it++) {
            int task = tid + it * 256;
            int r = task >> 3, g = task & 7;
            uint32_t soff = r * RB + ((g ^ (r & 7)) << 4);
            const __half* src = g_xh + (size_t)s_row[r] * I_SZ + ko + g * 8;
            CP16(dstA + soff, src);
        }
        // W: 128 rows x 8 granules = 1024 tasks
        const __half* sw = wsrc0 + ko;
#pragma unroll
        for (int it = 0; it < 4; it++) {
            int task = tid + it * 256;
            int r = task >> 3, g = task & 7;
            uint32_t soff = r * RB + ((g ^ (r & 7)) << 4);
            CP16(dstW + soff, sw + (size_t)r * I_SZ + g * 8);
        }
        CP_COMMIT();
    };

    fill(0, 0);
    fill(1, 1);
    fill(2, 2);

    float acc[2][4][4];
#pragma unroll
    for (int i = 0; i < 2; i++)
#pragma unroll
        for (int j = 0; j < 4; j++)
#pragma unroll
            for (int q = 0; q < 4; q++) acc[i][j][q] = 0.0f;

    uint32_t arow[2], brow[2];
    const int ahi = lane >> 4;
    const int bhi = (lane >> 3) & 1;
#pragma unroll
    for (int mt = 0; mt < 2; mt++)
        arow[mt] = wm * 32 + mt * 16 + (lane & 15);
#pragma unroll
    for (int p = 0; p < 2; p++)
        brow[p] = wn * 32 + p * 16 + (lane >> 4) * 8 + (lane & 7);

    auto compute = [&](int stage) {
        const uint32_t ab = sb + OFF_PIPE + stage * STAGE;
        const uint32_t wb = ab + A_CH;
#pragma unroll
        for (int j = 0; j < 4; j++) {
            uint32_t a[2][4], b[2][4];
#pragma unroll
            for (int mt = 0; mt < 2; mt++) {
                uint32_t g = (uint32_t)(j * 2 + ahi);
                uint32_t addr = ab + arow[mt] * RB +
                                ((g ^ (arow[mt] & 7)) << 4);
                LDSM_X4(a[mt][0], a[mt][1], a[mt][2], a[mt][3], addr);
            }
#pragma unroll
            for (int p = 0; p < 2; p++) {
                uint32_t g = (uint32_t)(j * 2 + bhi);
                uint32_t addr = wb + brow[p] * RB +
                                ((g ^ (brow[p] & 7)) << 4);
                LDSM_X4(b[p][0], b[p][1], b[p][2], b[p][3], addr);
            }
#pragma unroll
            for (int mt = 0; mt < 2; mt++) {
#pragma unroll
                for (int nt = 0; nt < 4; nt++) {
                    uint32_t b0 = b[nt >> 1][(nt & 1) * 2 + 0];
                    uint32_t b1 = b[nt >> 1][(nt & 1) * 2 + 1];
                    MMA16816(acc[mt][nt][0], acc[mt][nt][1],
                             acc[mt][nt][2], acc[mt][nt][3],
                             a[mt][0], a[mt][1], a[mt][2], a[mt][3], b0, b1);
                }
            }
        }
    };

    CP_WAIT(2);
    __syncthreads();
    compute(0);
    __syncthreads();
    fill(3, 0);
    CP_WAIT(2);
    __syncthreads();
    compute(1);
    CP_WAIT(1);
    __syncthreads();
    compute(2);
    CP_WAIT(0);
    __syncthreads();
    compute(0);

    const int g = lane >> 2, tq = lane & 3;
#pragma unroll
    for (int mt = 0; mt < 2; mt++) {
        int rl = wm * 32 + mt * 16 + g;
#pragma unroll
        for (int h = 0; h < 2; h++) {
            int rr = rl + h * 8;
            if (rr < rows) {
                float* op = out + (size_t)s_row[rr] * O_SZ + n0;
#pragma unroll
                for (int nt = 0; nt < 4; nt++) {
                    int cl = wn * 32 + nt * 8 + 2 * tq;
                    float2 v;
                    v.x = acc[mt][nt][h * 2 + 0] + s_bias[cl + 0];
                    v.y = acc[mt][nt][h * 2 + 1] + s_bias[cl + 1];
                    *(float2*)(op + cl) = v;
                }
            }
        }
    }
}

// ---------------------------------------------------------------------------
// launch: 2 kernels
// ---------------------------------------------------------------------------
extern "C" void kernel_launch(void* const* d_in, const int* in_sizes, int n_in,
                              void* d_out, int out_size) {
    const float* x      = (const float*)d_in[0];
    const void*  idx    = d_in[1];
    const float* weight = (const float*)d_in[2];
    const float* bias   = (const float*)d_in[3];
    float* out = (float*)d_out;

    cudaFuncSetAttribute(gemm_mma_kernel,
                         cudaFuncAttributeMaxDynamicSharedMemorySize, SM_TOTAL);

    k_prelude<<<800, 256>>>(x, idx, weight);
    dim3 grid(MAX_TILES, 2);
    gemm_mma_kernel<<<grid, 256, SM_TOTAL>>>(bias, out);
}

// round 13
// speedup vs baseline: 1.8995x; 1.0090x over previous
#include <cuda_runtime.h>
#include <cuda_fp16.h>
#include <cstdint>

#define B_SZ 8192
#define I_SZ 256
#define O_SZ 256
#define C_SZ 32
#define FULLMASK 0xFFFFFFFFu
#define MAX_TILES 160
#define TILE_M 64
#define TILE_N 64
#define PREP_NB 32

// ---------------- scratch (device globals; allocation-free) ----------------
__device__ int g_perm[B_SZ];
__device__ int g_offset[C_SZ];
__device__ int g_tiles[MAX_TILES];
__device__ int g_ntiles;
__device__ int g_is64;
__device__ int g_ok64[PREP_NB];
__device__ int g_bh64[PREP_NB * 32];
__device__ int g_bh32[PREP_NB * 32];
__device__ __half g_wq[C_SZ * O_SZ * I_SZ];   // [c][o][i] fp16
__device__ __half g_xh[B_SZ * I_SZ];          // x fp16, UNPERMUTED

__device__ unsigned p_bcnt;
__device__ volatile unsigned p_bgen;

// ---------------------------------------------------------------------------
// k_prelude: blocks 0..31 idx sort; 32..543 convert x; 544..799 conv_w
// ---------------------------------------------------------------------------
__global__ __launch_bounds__(256, 2)
void k_prelude(const float* __restrict__ x,
               const void* __restrict__ idx_ptr,
               const float* __restrict__ weight) {
    __shared__ char sbuf[17152];
    const int b = blockIdx.x;
    const int tid = threadIdx.x;

    if (b >= 32 && b < 544) {
        const int thr = (b - 32) * 256 + tid;
#pragma unroll
        for (int it = 0; it < 2; it++) {
            int g = thr + it * 131072;
            const float4* s = (const float4*)x + (size_t)g * 2;
            float4 v0 = s[0], v1 = s[1];
            union { uint4 u; __half2 h[4]; } P;
            P.h[0] = __float22half2_rn(make_float2(v0.x, v0.y));
            P.h[1] = __float22half2_rn(make_float2(v0.z, v0.w));
            P.h[2] = __float22half2_rn(make_float2(v1.x, v1.y));
            P.h[3] = __float22half2_rn(make_float2(v1.z, v1.w));
            ((uint4*)g_xh)[g] = P.u;
        }
        return;
    }

    if (b >= 544) {
        __half* sh = (__half*)sbuf;
        const int o = b - 544;
        const float* src = weight + (size_t)o * (I_SZ * C_SZ);
        for (int l = tid; l < I_SZ * C_SZ; l += 256) {
            int i = l >> 5, c = l & 31;
            sh[i * 33 + c] = __float2half_rn(src[l]);
        }
        __syncthreads();
        for (int u = tid; u < (I_SZ * C_SZ) / 4; u += 256) {
            int c = u >> 6, i4 = u & 63;
            union { uint2 uu; __half h[4]; } H;
#pragma unroll
            for (int j = 0; j < 4; j++)
                H.h[j] = sh[(i4 * 4 + j) * 33 + c];
            size_t off = ((size_t)c << 16) + ((size_t)o << 8) + (size_t)i4 * 4;
            *(uint2*)(g_wq + off) = H.uu;
        }
        return;
    }

    // ======================= prep (blocks 0..31) ===========================
    int* s_h64 = (int*)sbuf;
    int* s_h32 = s_h64 + 256;
    int* s_wb  = s_h32 + 256;
    int* s_vote = s_wb + 256;
    int* s_flag = s_vote + 8;

    const int w = tid >> 5;
    const int lane = tid & 31;
    const int e = b * 256 + tid;

    if (w == 0 && lane < 8) s_vote[lane] = 0;
    s_h64[w * 32 + lane] = 0;
    s_h32[w * 32 + lane] = 0;
    __syncthreads();

    const int v32 = ((const int*)idx_ptr)[e];
    const int2 v64 = ((const int2*)idx_ptr)[e];

    {
        int ok64 = (v64.y == 0) && ((unsigned)v64.x < 32u);
        int allok = __all_sync(FULLMASK, ok64);
        if (lane == 0) s_vote[w] = allok;
    }
    {
        int c = v64.x & 31;
        unsigned m = __match_any_sync(FULLMASK, c);
        if (lane == (__ffs(m) - 1)) s_h64[w * 32 + c] += __popc(m);
    }
    {
        int c = v32 & 31;
        unsigned m = __match_any_sync(FULLMASK, c);
        if (lane == (__ffs(m) - 1)) s_h32[w * 32 + c] += __popc(m);
    }
    __syncthreads();

    if (tid < 32) {
        int t64 = 0, t32 = 0;
#pragma unroll
        for (int w2 = 0; w2 < 8; w2++) {
            t64 += s_h64[w2 * 32 + tid];
            t32 += s_h32[w2 * 32 + tid];
        }
        g_bh64[b * 32 + tid] = t64;
        g_bh32[b * 32 + tid] = t32;
        if (tid == 0) {
            int a = 1;
#pragma unroll
            for (int i = 0; i < 8; i++) a &= s_vote[i];
            g_ok64[b] = a;
        }
    }

    __syncthreads();
    if (tid == 0) {
        unsigned my = p_bgen;
        __threadfence();
        if (atomicAdd(&p_bcnt, 1u) == PREP_NB - 1) {
            p_bcnt = 0;
            __threadfence();
            p_bgen = my + 1;
        } else {
            while (p_bgen == my) {}
            __threadfence();
        }
    }
    __syncthreads();

    if (tid < 32) {
        int v = g_ok64[tid];
        v = __all_sync(FULLMASK, v);
        if (tid == 0) s_flag[0] = v;
    }
    __syncthreads();
    const int is64 = s_flag[0];
    const int* BH = is64 ? g_bh64 : g_bh32;
    int* s_hsel = is64 ? s_h64 : s_h32;

    if (tid < 32) {
        const int c = tid;
        int tot = 0, before = 0;
#pragma unroll
        for (int b2 = 0; b2 < PREP_NB; b2++) {
            int h = BH[b2 * 32 + c];
            if (b2 < b) before += h;
            tot += h;
        }
        int incl = tot;
#pragma unroll
        for (int d = 1; d < 32; d <<= 1) {
            int u = __shfl_up_sync(FULLMASK, incl, d);
            if (lane >= d) incl += u;
        }
        int off = incl - tot;
        int run = off + before;
#pragma unroll
        for (int w2 = 0; w2 < 8; w2++) {
            s_wb[w2 * 32 + c] = run;
            run += s_hsel[w2 * 32 + c];
        }
        if (b == 0) {
            g_offset[c] = off;
            if (c == 0) g_is64 = is64;
            if (lane == 0) {
                int nt = 0;
                for (int cc = 0; cc < 32; cc++) {
                    int cnt = 0;
                    for (int b2 = 0; b2 < PREP_NB; b2++) cnt += BH[b2 * 32 + cc];
                    for (int m = 0; m * TILE_M < cnt; m++) {
                        int rows = min(TILE_M, cnt - m * TILE_M);
                        g_tiles[nt++] = cc | (m << 8) | (rows << 16);
                    }
                }
                g_ntiles = nt;
            }
        }
    }
    __syncthreads();

    {
        int c = is64 ? (v64.x & 31) : (v32 & 31);
        unsigned m = __match_any_sync(FULLMASK, c);
        int rank = __popc(m & ((1u << lane) - 1u));
        int base = s_wb[w * 32 + c];
        g_perm[base + rank] = e;
    }
}

// ---------------------------------------------------------------------------
// GEMM: 64x64xK256 tiles, cp.async 3-stage, swizzled 128B rows, 4 CTAs/SM.
// 8 warps = 4m x 2n; warp tile 16 rows x 32 cols.
// ---------------------------------------------------------------------------
#define RB 128
#define A_CH (TILE_M * RB)               // 8192
#define W_CH (TILE_N * RB)               // 8192
#define STAGE (A_CH + W_CH)              // 16384
#define OFF_ROW  0                       // 64 ints
#define OFF_BIAS 256                     // 64 floats
#define OFF_PIPE 512
#define SM_TOTAL (OFF_PIPE + 3 * STAGE)  // 49664

__device__ __forceinline__ uint32_t smem_u32(const void* p) {
    uint32_t a;
    asm("{ .reg .u64 t; cvta.to.shared.u64 t, %1; cvt.u32.u64 %0, t; }"
        : "=r"(a) : "l"(p));
    return a;
}

#define CP16(dst, src) \
    asm volatile("cp.async.cg.shared.global [%0], [%1], 16;" \
                 :: "r"(dst), "l"(src) : "memory")
#define CP_COMMIT() asm volatile("cp.async.commit_group;" ::: "memory")
#define CP_WAIT(n)  asm volatile("cp.async.wait_group %0;" :: "n"(n) : "memory")

#define LDSM_X4(r0, r1, r2, r3, addr)                                       \
    asm volatile("ldmatrix.sync.aligned.m8n8.x4.shared.b16 "                \
                 "{%0,%1,%2,%3}, [%4];"                                     \
                 : "=r"(r0), "=r"(r1), "=r"(r2), "=r"(r3) : "r"(addr))

#define MMA16816(d0, d1, d2, d3, a0, a1, a2, a3, b0, b1)                    \
    asm volatile("mma.sync.aligned.m16n8k16.row.col.f32.f16.f16.f32 "       \
                 "{%0,%1,%2,%3}, {%4,%5,%6,%7}, {%8,%9}, {%0,%1,%2,%3};"    \
                 : "+f"(d0), "+f"(d1), "+f"(d2), "+f"(d3)                   \
                 : "r"(a0), "r"(a1), "r"(a2), "r"(a3), "r"(b0), "r"(b1))

__global__ __launch_bounds__(256, 4)
void gemm_mma_kernel(const float* __restrict__ bias, float* __restrict__ out) {
    extern __shared__ char smem[];
    if ((int)blockIdx.x >= g_ntiles) return;
    const int t = g_tiles[blockIdx.x];
    const int c = t & 31;
    const int m0 = ((t >> 8) & 0xFF) * TILE_M;
    const int rows = (t >> 16) & 0xFF;
    const int base = g_offset[c] + m0;
    const int n0 = blockIdx.y * TILE_N;

    const int tid = threadIdx.x;
    const int wid = tid >> 5;
    const int lane = tid & 31;
    const int wm = wid >> 1;      // 0..3, 16 rows each
    const int wn = wid & 1;       // 0..1, 32 cols each

    int* s_row = (int*)(smem + OFF_ROW);
    float* s_bias = (float*)(smem + OFF_BIAS);
    const uint32_t sb = smem_u32(smem);

    if (tid < TILE_M) s_row[tid] = g_perm[base + min(tid, rows - 1)];
    if (tid < TILE_N) s_bias[tid] = bias[(size_t)(n0 + tid) * C_SZ + c];
    __syncthreads();

    const __half* wsrc0 = g_wq + ((size_t)c << 16) + (size_t)n0 * I_SZ;

    auto fill = [&](int kc, int stage) {
        const uint32_t dstA = sb + OFF_PIPE + stage * STAGE;
        const uint32_t dstW = dstA + A_CH;
        const int ko = kc * 64;
        // A: 64 rows x 8 granules = 512 tasks
#pragma unroll
        for (int it = 0; it < 2; it++) {
            int task = tid + it * 256;
            int r = task >> 3, g = task & 7;
            uint32_t soff = r * RB + ((g ^ (r & 7)) << 4);
            const __half* src = g_xh + (size_t)s_row[r] * I_SZ + ko + g * 8;
            CP16(dstA + soff, src);
        }
        // W: 64 rows x 8 granules = 512 tasks
        const __half* sw = wsrc0 + ko;
#pragma unroll
        for (int it = 0; it < 2; it++) {
            int task = tid + it * 256;
            int r = task >> 3, g = task & 7;
            uint32_t soff = r * RB + ((g ^ (r & 7)) << 4);
            CP16(dstW + soff, sw + (size_t)r * I_SZ + g * 8);
        }
        CP_COMMIT();
    };

    fill(0, 0);
    fill(1, 1);
    fill(2, 2);

    float acc[4][4];      // [nt][q]
#pragma unroll
    for (int j = 0; j < 4; j++)
#pragma unroll
        for (int q = 0; q < 4; q++) acc[j][q] = 0.0f;

    const uint32_t arow = wm * 16 + (lane & 15);
    const int ahi = lane >> 4;
    uint32_t brow[2];
    const int bhi = (lane >> 3) & 1;
#pragma unroll
    for (int p = 0; p < 2; p++)
        brow[p] = wn * 32 + p * 16 + (lane >> 4) * 8 + (lane & 7);

    auto compute = [&](int stage) {
        const uint32_t ab = sb + OFF_PIPE + stage * STAGE;
        const uint32_t wb = ab + A_CH;
#pragma unroll
        for (int j = 0; j < 4; j++) {
            uint32_t a[4], b[2][4];
            {
                uint32_t g = (uint32_t)(j * 2 + ahi);
                uint32_t addr = ab + arow * RB + ((g ^ (arow & 7)) << 4);
                LDSM_X4(a[0], a[1], a[2], a[3], addr);
            }
#pragma unroll
            for (int p = 0; p < 2; p++) {
                uint32_t g = (uint32_t)(j * 2 + bhi);
                uint32_t addr = wb + brow[p] * RB + ((g ^ (brow[p] & 7)) << 4);
                LDSM_X4(b[p][0], b[p][1], b[p][2], b[p][3], addr);
            }
#pragma unroll
            for (int nt = 0; nt < 4; nt++) {
                uint32_t b0 = b[nt >> 1][(nt & 1) * 2 + 0];
                uint32_t b1 = b[nt >> 1][(nt & 1) * 2 + 1];
                MMA16816(acc[nt][0], acc[nt][1], acc[nt][2], acc[nt][3],
                         a[0], a[1], a[2], a[3], b0, b1);
            }
        }
    };

    CP_WAIT(2);
    __syncthreads();
    compute(0);
    __syncthreads();
    fill(3, 0);
    CP_WAIT(2);
    __syncthreads();
    compute(1);
    CP_WAIT(1);
    __syncthreads();
    compute(2);
    CP_WAIT(0);
    __syncthreads();
    compute(0);

    const int g = lane >> 2, tq = lane & 3;
    const int rl = wm * 16 + g;
#pragma unroll
    for (int h = 0; h < 2; h++) {
        int rr = rl + h * 8;
        if (rr < rows) {
            float* op = out + (size_t)s_row[rr] * O_SZ + n0;
#pragma unroll
            for (int nt = 0; nt < 4; nt++) {
                int cl = wn * 32 + nt * 8 + 2 * tq;
                float2 v;
                v.x = acc[nt][h * 2 + 0] + s_bias[cl + 0];
                v.y = acc[nt][h * 2 + 1] + s_bias[cl + 1];
                *(float2*)(op + cl) = v;
            }
        }
    }
}

// ---------------------------------------------------------------------------
// launch: 2 kernels
// ---------------------------------------------------------------------------
extern "C" void kernel_launch(void* const* d_in, const int* in_sizes, int n_in,
                              void* d_out, int out_size) {
    const float* x      = (const float*)d_in[0];
    const void*  idx    = d_in[1];
    const float* weight = (const float*)d_in[2];
    const float* bias   = (const float*)d_in[3];
    float* out = (float*)d_out;

    cudaFuncSetAttribute(gemm_mma_kernel,
                         cudaFuncAttributeMaxDynamicSharedMemorySize, SM_TOTAL);

    k_prelude<<<800, 256>>>(x, idx, weight);
    dim3 grid(MAX_TILES, O_SZ / TILE_N);   // 160 x 4
    gemm_mma_kernel<<<grid, 256, SM_TOTAL>>>(bias, out);
}